// round 6
// baseline (speedup 1.0000x reference)
#include <cuda_runtime.h>
#include <math.h>

#define N_STATES      25
#define LUT_PITCH     64   // pitch multiple of 32 banks -> bank = x % 32; obs<50 => <=2 values per bank
#define LUT_SIZE      (N_STATES * LUT_PITCH)
#define BLOCK_THREADS 256

// Scratch LUT (allocation-free rule: __device__ global).
__device__ float g_lut[LUT_SIZE];

// Build the 25x64 log-prob table in fp32 (few-ulp accurate, >>1e-3 margin).
__global__ void build_lut_kernel(const float* __restrict__ means,
                                 const float* __restrict__ phis) {
    int idx = blockIdx.x * blockDim.x + threadIdx.x;
    if (idx >= LUT_SIZE) return;
    int s = idx / LUT_PITCH;
    int x = idx % LUT_PITCH;
    float v;
    if (s == 0) {
        v = (x > 0) ? -100000.0f : 0.0f;
    } else {
        float mu  = means[s];
        float phi = phis[s];
        float xf  = (float)x;
        float inv = 1.0f / (phi + mu);
        v = lgammaf(xf + phi) - lgammaf(phi) - lgammaf(xf + 1.0f)
          + phi * logf(phi * inv)
          + xf  * logf(mu  * inv);
    }
    g_lut[idx] = v;
}

// Main kernel: out[s][i] = LUT[s][obs[i]].
// One int4 group (4 spots) per thread, deep oversubscription (~26 blocks/SM
// queued). Row 0 (bookend) is computed arithmetically; rows 1..24 gathered
// from the shared-memory LUT. minBlocksPerMultiprocessor=8 caps regs at 32
// so 8 blocks (64 warps) fit per SM.
__global__ void __launch_bounds__(BLOCK_THREADS, 8)
emit_kernel(const int* __restrict__ obs,
            float* __restrict__ out,
            int n_groups,        // ceil-range over n_spots/4 groups
            long long n_spots) {
    __shared__ float lut[LUT_SIZE];
    #pragma unroll
    for (int i = threadIdx.x; i < LUT_SIZE; i += BLOCK_THREADS)
        lut[i] = g_lut[i];
    __syncthreads();

    int g = blockIdx.x * BLOCK_THREADS + threadIdx.x;
    if (g >= n_groups) return;

    int4 o = ((const int4*)obs)[g];

    // Row 0: bookend, pure ALU (no smem traffic).
    {
        float4 v;
        v.x = (o.x > 0) ? -100000.0f : 0.0f;
        v.y = (o.y > 0) ? -100000.0f : 0.0f;
        v.z = (o.z > 0) ? -100000.0f : 0.0f;
        v.w = (o.w > 0) ? -100000.0f : 0.0f;
        ((float4*)out)[g] = v;
    }

    #pragma unroll
    for (int s = 1; s < N_STATES; s++) {
        const float* row = lut + s * LUT_PITCH;
        float4 v;
        v.x = row[o.x];
        v.y = row[o.y];
        v.z = row[o.z];
        v.w = row[o.w];
        ((float4*)(out + (long long)s * n_spots))[g] = v;
    }
}

// Scalar fallback only if n_spots % 4 != 0 (never hit for N_SPOTS=4M).
__global__ void emit_tail_kernel(const int* __restrict__ obs,
                                 float* __restrict__ out,
                                 int tail_start, int n_spots_i,
                                 long long n_spots) {
    int i = tail_start + blockIdx.x * blockDim.x + threadIdx.x;
    if (i >= n_spots_i) return;
    int x = obs[i];
    #pragma unroll
    for (int s = 0; s < N_STATES; s++)
        out[(long long)s * n_spots + i] = g_lut[s * LUT_PITCH + x];
}

extern "C" void kernel_launch(void* const* d_in, const int* in_sizes, int n_in,
                              void* d_out, int out_size) {
    const float* state_means = (const float*)d_in[0];
    const float* state_phis  = (const float*)d_in[1];
    const int*   obs         = (const int*)d_in[2];
    float*       out         = (float*)d_out;

    int n_spots_i = in_sizes[2];
    long long n_spots = (long long)n_spots_i;

    build_lut_kernel<<<(LUT_SIZE + 255) / 256, 256>>>(state_means, state_phis);

    int n_groups = n_spots_i / 4;
    if (n_groups > 0) {
        int blocks = (n_groups + BLOCK_THREADS - 1) / BLOCK_THREADS;
        emit_kernel<<<blocks, BLOCK_THREADS>>>(obs, out, n_groups, n_spots);
    }

    int tail_start = n_groups * 4;
    int tail = n_spots_i - tail_start;
    if (tail > 0) {
        emit_tail_kernel<<<(tail + 255) / 256, 256>>>(obs, out, tail_start,
                                                      n_spots_i, n_spots);
    }
}